// round 15
// baseline (speedup 1.0000x reference)
#include <cuda_runtime.h>
#include <math.h>
#include <stdint.h>

#define N_TOK 2048
#define HDIM  1024
#define FDIM  1024
#define NE    8
#define TOPK  2
#define SLOTS (NE * N_TOK)

// ---------------- device scratch (static: no allocations allowed) -----------
__device__ int   d_mask;
__device__ int   d_cnt[NE];
__device__ int   d_map[NE];
__device__ int   d_tok[SLOTS];
__device__ int   d_top_i[N_TOK * TOPK];
__device__ float d_top_w[N_TOK * TOPK];
__device__ int   d_pair_slot[N_TOK * TOPK];
__device__ float d_pair_w[N_TOK * TOPK];

// int8 limb arrays (packed 4 per uint32; row = 256 uint32)
__device__ uint32_t d_xq1[(size_t)N_TOK * 256];        // 2 MB
__device__ uint32_t d_xq2[(size_t)N_TOK * 256];
__device__ float    d_sx[N_TOK];
__device__ uint32_t d_gq1[(size_t)NE * 2048 * 256];    // 16 MB
__device__ uint32_t d_gq2[(size_t)NE * 2048 * 256];
__device__ float    d_sg[NE * 2048];
__device__ uint32_t d_dq1[(size_t)NE * 1024 * 256];    // 8 MB
__device__ uint32_t d_dq2[(size_t)NE * 1024 * 256];
__device__ float    d_sd[NE * 1024];
__device__ uint32_t d_hq1[(size_t)SLOTS * 256];        // 16 MB
__device__ uint32_t d_hq2[(size_t)SLOTS * 256];
__device__ float    d_sh[SLOTS];

__device__ float d_hmid[(size_t)SLOTS * FDIM];         // 64 MB
__device__ float d_y   [(size_t)SLOTS * HDIM];         // 64 MB

// ---------------- tiny setup kernels ----------------------------------------
__global__ void init_kernel() {
    if (threadIdx.x == 0) d_mask = 0;
}

__global__ void router_kernel(const float* __restrict__ x,
                              const float* __restrict__ gw) {
    int n   = blockIdx.x;
    int tid = threadIdx.x;
    const float* xr = x + (size_t)n * HDIM;

    float p[NE];
#pragma unroll
    for (int e = 0; e < NE; ++e) p[e] = 0.f;

    for (int h = tid; h < HDIM; h += 128) {
        float xv = xr[h];
#pragma unroll
        for (int e = 0; e < NE; ++e)
            p[e] = fmaf(xv, gw[e * HDIM + h], p[e]);
    }
#pragma unroll
    for (int e = 0; e < NE; ++e)
#pragma unroll
        for (int o = 16; o > 0; o >>= 1)
            p[e] += __shfl_xor_sync(0xffffffffu, p[e], o);

    __shared__ float sh[NE][4];
    int w = tid >> 5, l = tid & 31;
    if (l == 0)
#pragma unroll
        for (int e = 0; e < NE; ++e) sh[e][w] = p[e];
    __syncthreads();

    if (tid == 0) {
        float lg[NE];
#pragma unroll
        for (int e = 0; e < NE; ++e)
            lg[e] = sh[e][0] + sh[e][1] + sh[e][2] + sh[e][3];
        float mx = lg[0];
#pragma unroll
        for (int e = 1; e < NE; ++e) mx = fmaxf(mx, lg[e]);
        float pr[NE], s = 0.f;
#pragma unroll
        for (int e = 0; e < NE; ++e) { pr[e] = expf(lg[e] - mx); s += pr[e]; }
        float inv = 1.f / s;
#pragma unroll
        for (int e = 0; e < NE; ++e) pr[e] *= inv;

        int i0 = 0;
#pragma unroll
        for (int e = 1; e < NE; ++e) if (pr[e] > pr[i0]) i0 = e;
        int i1 = -1;
#pragma unroll
        for (int e = 0; e < NE; ++e)
            if (e != i0 && (i1 < 0 || pr[e] > pr[i1])) i1 = e;

        float w0 = pr[i0], w1 = pr[i1];
        float den = fmaxf(w0 + w1, 1e-12f);
        w0 /= den; w1 /= den;

        d_top_i[2 * n]     = i0;
        d_top_i[2 * n + 1] = i1;
        d_top_w[2 * n]     = w0;
        d_top_w[2 * n + 1] = w1;
        atomicOr(&d_mask, 1 << i0);
    }
}

__global__ void map_kernel(const float* __restrict__ sim) {
    int e = threadIdx.x;
    if (e < NE) {
        d_cnt[e] = 0;
        int mask = d_mask;
        int m;
        if ((mask >> e) & 1) {
            m = e;
        } else {
            float best = -INFINITY; int bj = -1;
#pragma unroll
            for (int j = 0; j < NE; ++j) {
                if ((mask >> j) & 1) {
                    float s = sim[e * NE + j];
                    if (s > best) { best = s; bj = j; }
                }
            }
            m = (bj >= 0 && best >= 0.7f) ? bj : e;
        }
        d_map[e] = m;
    }
}

__global__ void assign_kernel() {
    int n = blockIdx.x * blockDim.x + threadIdx.x;
    if (n >= N_TOK) return;
    int   i0 = d_top_i[2 * n],     i1 = d_top_i[2 * n + 1];
    float w0 = d_top_w[2 * n],     w1 = d_top_w[2 * n + 1];
    int   e0 = d_map[i0],          e1 = d_map[i1];

    if (e0 == e1) {
        int idx = atomicAdd(&d_cnt[e0], 1);
        int s   = e0 * N_TOK + idx;
        d_tok[s] = n;
        d_pair_slot[2 * n]     = s;   d_pair_w[2 * n]     = w0 + w1;
        d_pair_slot[2 * n + 1] = -1;  d_pair_w[2 * n + 1] = 0.f;
    } else {
        int idx0 = atomicAdd(&d_cnt[e0], 1);
        int idx1 = atomicAdd(&d_cnt[e1], 1);
        int s0 = e0 * N_TOK + idx0, s1 = e1 * N_TOK + idx1;
        d_tok[s0] = n;
        d_tok[s1] = n;
        d_pair_slot[2 * n]     = s0;  d_pair_w[2 * n]     = w0;
        d_pair_slot[2 * n + 1] = s1;  d_pair_w[2 * n + 1] = w1;
    }
}

// ---------------- row quantization -------------------------------------------
// a = s*(q1 + q2/64), q1 in [-127,127], q2 in [-32,32]; row = 1024 floats.
__device__ __forceinline__ void quant_row_body(const float* __restrict__ row,
                                               uint32_t* __restrict__ q1,
                                               uint32_t* __restrict__ q2,
                                               float* __restrict__ s_out,
                                               int tid) {
    const float4 v = *(const float4*)(row + tid * 4);
    float m = fmaxf(fmaxf(fabsf(v.x), fabsf(v.y)), fmaxf(fabsf(v.z), fabsf(v.w)));
#pragma unroll
    for (int o = 16; o > 0; o >>= 1) m = fmaxf(m, __shfl_xor_sync(0xffffffffu, m, o));
    __shared__ float sm[8];
    if ((tid & 31) == 0) sm[tid >> 5] = m;
    __syncthreads();
    float rm = fmaxf(fmaxf(fmaxf(sm[0], sm[1]), fmaxf(sm[2], sm[3])),
                     fmaxf(fmaxf(sm[4], sm[5]), fmaxf(sm[6], sm[7])));
    float inv = rm > 0.f ? 127.f / rm : 0.f;
    if (tid == 0) *s_out = rm / 127.f;

    float t[4] = {v.x * inv, v.y * inv, v.z * inv, v.w * inv};
    uint32_t p1 = 0, p2 = 0;
#pragma unroll
    for (int i = 0; i < 4; ++i) {
        int a = __float2int_rn(t[i]);
        a = max(-127, min(127, a));
        int b = __float2int_rn((t[i] - (float)a) * 64.f);
        b = max(-127, min(127, b));
        p1 |= ((uint32_t)a & 0xFFu) << (8 * i);
        p2 |= ((uint32_t)b & 0xFFu) << (8 * i);
    }
    q1[tid] = p1;
    q2[tid] = p2;
}

__global__ void quant_rows(const float* __restrict__ W, uint32_t* __restrict__ q1,
                           uint32_t* __restrict__ q2, float* __restrict__ s) {
    size_t row = blockIdx.x;
    quant_row_body(W + row * 1024, q1 + row * 256, q2 + row * 256, s + row,
                   threadIdx.x);
}

__global__ void quant_h_kernel() {
    int e = blockIdx.y, m = blockIdx.x;
    if (m >= d_cnt[e]) return;
    size_t row = (size_t)e * N_TOK + m;
    quant_row_body(d_hmid + row * 1024, d_hq1 + row * 256, d_hq2 + row * 256,
                   d_sh + row, threadIdx.x);
}

// ---------------- int8 tensor-core GEMM common -------------------------------
// SMEM rows: 64 int8 data padded to 80 bytes (5x16B -> conflict-free ldmatrix).
#define LDR   80
#define ASZ8  (128 * LDR)            // 10240: A limb tile (128 rows)
#define BSZ8  (64 * LDR)             // 5120 : B limb tile (64 rows)
#define STG8  (2 * ASZ8 + 2 * BSZ8)  // 30720 per stage
#define SMEM8 (2 * STG8)             // 61440 double buffered

#define LDSM4(r, addr) \
    asm volatile("ldmatrix.sync.aligned.m8n8.x4.shared.b16 {%0,%1,%2,%3}, [%4];" \
        : "=r"((r)[0]), "=r"((r)[1]), "=r"((r)[2]), "=r"((r)[3]) : "r"(addr))

#define MMA_S8(c, a, b0, b1) \
    asm volatile("mma.sync.aligned.m16n8k32.row.col.s32.s8.s8.s32 " \
        "{%0,%1,%2,%3},{%4,%5,%6,%7},{%8,%9},{%0,%1,%2,%3};" \
        : "+r"((c)[0]), "+r"((c)[1]), "+r"((c)[2]), "+r"((c)[3]) \
        : "r"((a)[0]), "r"((a)[1]), "r"((a)[2]), "r"((a)[3]), "r"(b0), "r"(b1))

__device__ __forceinline__ float silu_f(float g) {
    return g / (1.f + expf(-g));
}

__device__ __forceinline__ float dec_i(int a1, int a2) {
    return (float)a1 + (float)a2 * 0.015625f;
}

// One k32 chunk: ldsm all limb fragments, 8 MMA into ACC1, 16 into ACC2.
#define CHUNK_S8(bufo_, koff_)                                                \
    do {                                                                      \
        uint32_t a1[2][4], a2[2][4], b1f[2][4], b2f[2][4];                    \
        _Pragma("unroll")                                                     \
        for (int mt = 0; mt < 2; ++mt) {                                      \
            uint32_t aaddr = sbase + (bufo_) + a_lane + mt * 16 * LDR + (koff_); \
            LDSM4(a1[mt], aaddr);                                             \
            LDSM4(a2[mt], aaddr + ASZ8);                                      \
        }                                                                     \
        _Pragma("unroll")                                                     \
        for (int bp = 0; bp < 2; ++bp) {                                      \
            uint32_t baddr = sbase + (bufo_) + 2 * ASZ8 + b_lane[bp] + (koff_); \
            LDSM4(b1f[bp], baddr);                                            \
            LDSM4(b2f[bp], baddr + BSZ8);                                     \
        }                                                                     \
        _Pragma("unroll")                                                     \
        for (int bp = 0; bp < 2; ++bp)                                        \
            _Pragma("unroll")                                                 \
            for (int mt = 0; mt < 2; ++mt) {                                  \
                MMA_S8(acc1[mt][2 * bp],     a1[mt], b1f[bp][0], b1f[bp][1]); \
                MMA_S8(acc1[mt][2 * bp + 1], a1[mt], b1f[bp][2], b1f[bp][3]); \
            }                                                                 \
        _Pragma("unroll")                                                     \
        for (int bp = 0; bp < 2; ++bp)                                        \
            _Pragma("unroll")                                                 \
            for (int mt = 0; mt < 2; ++mt) {                                  \
                MMA_S8(acc2[mt][2 * bp],     a1[mt], b2f[bp][0], b2f[bp][1]); \
                MMA_S8(acc2[mt][2 * bp + 1], a1[mt], b2f[bp][2], b2f[bp][3]); \
                MMA_S8(acc2[mt][2 * bp],     a2[mt], b1f[bp][0], b1f[bp][1]); \
                MMA_S8(acc2[mt][2 * bp + 1], a2[mt], b1f[bp][2], b1f[bp][3]); \
            }                                                                 \
    } while (0)

// ---------------- GEMM1 (int8): x @ gate_up^T -> silu(g)*u -> hmid fp32 ------
// CTA: 128 tokens x 32 hmid cols. B tile 64 rows: per warp_n 32-row span =
// [16 gate rows | 16 up rows] for the same output columns.
__global__ __launch_bounds__(256)
void gemm1_i8() {
    int e   = blockIdx.z;
    int cnt = d_cnt[e];
    int m0  = blockIdx.y * 128;
    if (m0 >= cnt) return;
    int j0  = blockIdx.x * 32;           // hmid column base

    extern __shared__ __align__(16) unsigned char smem[];
    uint32_t sbase = (uint32_t)__cvta_generic_to_shared(smem);

    int tid  = threadIdx.x;
    int lane = tid & 31;
    int wid  = tid >> 5;
    int warp_m = wid & 3;
    int warp_n = wid >> 2;

    // A loader: thread owns 32-byte half-row per limb
    int  m_l  = tid >> 1;
    int  half = tid & 1;
    int  am   = m0 + m_l;
    bool av   = (am < cnt);
    int  tok  = av ? d_tok[e * N_TOK + am] : 0;
    const uint4* a1p = (const uint4*)(d_xq1 + (size_t)tok * 256) + half * 2;
    const uint4* a2p = (const uint4*)(d_xq2 + (size_t)tok * 256) + half * 2;
    uint32_t sts_a = (uint32_t)(m_l * LDR + half * 32);

    // B loader: thread owns 16 bytes of one of 64 rows
    int b_l = tid >> 2;
    int bq  = tid & 3;
    int wn  = b_l >> 5, bt = b_l & 31;
    int wr  = (bt < 16) ? (j0 + wn * 16 + bt) : (1024 + j0 + wn * 16 + (bt - 16));
    size_t growbase = ((size_t)e * 2048 + wr) * 256;
    const uint4* b1p = (const uint4*)(d_gq1 + growbase) + bq;
    const uint4* b2p = (const uint4*)(d_gq2 + growbase) + bq;
    uint32_t sts_b = (uint32_t)(b_l * LDR + bq * 16);

    // prologue
    uint4 pa1[2], pa2[2], pb1, pb2;
    const uint4 zu = make_uint4(0, 0, 0, 0);
    pa1[0] = av ? a1p[0] : zu;  pa1[1] = av ? a1p[1] : zu;
    pa2[0] = av ? a2p[0] : zu;  pa2[1] = av ? a2p[1] : zu;
    pb1 = b1p[0];  pb2 = b2p[0];

    *(uint4*)(smem + sts_a)              = pa1[0];
    *(uint4*)(smem + sts_a + 16)         = pa1[1];
    *(uint4*)(smem + ASZ8 + sts_a)       = pa2[0];
    *(uint4*)(smem + ASZ8 + sts_a + 16)  = pa2[1];
    *(uint4*)(smem + 2 * ASZ8 + sts_b)          = pb1;
    *(uint4*)(smem + 2 * ASZ8 + BSZ8 + sts_b)   = pb2;
    __syncthreads();

    int acc1[2][4][4], acc2[2][4][4];
#pragma unroll
    for (int i = 0; i < 2; ++i)
#pragma unroll
        for (int j = 0; j < 4; ++j)
#pragma unroll
            for (int q = 0; q < 4; ++q) { acc1[i][j][q] = 0; acc2[i][j][q] = 0; }

    uint32_t a_lane = (warp_m * 32 + (lane & 15)) * LDR + (lane >> 4) * 16;
    uint32_t b_lane[2];
#pragma unroll
    for (int bp = 0; bp < 2; ++bp)
        b_lane[bp] = (warp_n * 32 + bp * 16 + (lane & 7) + ((lane >> 4) & 1) * 8) * LDR
                     + ((lane >> 3) & 1) * 16;

    const int KT = 16;                   // 1024 / 64
    uint32_t bufo = 0;
    for (int kt = 0; kt < KT; ++kt) {
        bool more = (kt + 1 < KT);
        if (more) {
            int ki = (kt + 1) * 4;       // uint4 index per row
            pa1[0] = av ? a1p[ki]     : zu;
            pa1[1] = av ? a1p[ki + 1] : zu;
            pa2[0] = av ? a2p[ki]     : zu;
            pa2[1] = av ? a2p[ki + 1] : zu;
            pb1 = b1p[ki];
            pb2 = b2p[ki];
        }

        CHUNK_S8(bufo, 0);
        CHUNK_S8(bufo, 32);

        if (more) {
            uint32_t nb = bufo ^ STG8;
            *(uint4*)(smem + nb + sts_a)              = pa1[0];
            *(uint4*)(smem + nb + sts_a + 16)         = pa1[1];
            *(uint4*)(smem + nb + ASZ8 + sts_a)       = pa2[0];
            *(uint4*)(smem + nb + ASZ8 + sts_a + 16)  = pa2[1];
            *(uint4*)(smem + nb + 2 * ASZ8 + sts_b)        = pb1;
            *(uint4*)(smem + nb + 2 * ASZ8 + BSZ8 + sts_b) = pb2;
            __syncthreads();
            bufo = nb;
        }
    }

    // epilogue: g,u -> silu(g)*u -> d_hmid fp32
    int rrow = warp_m * 32 + (lane >> 2);
#pragma unroll
    for (int mt = 0; mt < 2; ++mt) {
        int r0 = m0 + rrow + mt * 16;
        int r1 = r0 + 8;
#pragma unroll
        for (int ntg = 0; ntg < 2; ++ntg) {
            int cl = j0 + warp_n * 16 + ntg * 8 + (lane & 3) * 2;
            float sg0 = d_sg[e * 2048 + cl];
            float sg1 = d_sg[e * 2048 + cl + 1];
            float su0 = d_sg[e * 2048 + 1024 + cl];
            float su1 = d_sg[e * 2048 + 1024 + cl + 1];
            int* g1a = acc1[mt][ntg];     int* g2a = acc2[mt][ntg];
            int* u1a = acc1[mt][ntg + 2]; int* u2a = acc2[mt][ntg + 2];
            if (r0 < cnt) {
                float sA = d_sx[d_tok[e * N_TOK + r0]];
                float g0 = sA * sg0 * dec_i(g1a[0], g2a[0]);
                float g1 = sA * sg1 * dec_i(g1a[1], g2a[1]);
                float u0 = sA * su0 * dec_i(u1a[0], u2a[0]);
                float u1 = sA * su1 * dec_i(u1a[1], u2a[1]);
                *(float2*)&d_hmid[(size_t)(e * N_TOK + r0) * FDIM + cl] =
                    make_float2(silu_f(g0) * u0, silu_f(g1) * u1);
            }
            if (r1 < cnt) {
                float sA = d_sx[d_tok[e * N_TOK + r1]];
                float g2 = sA * sg0 * dec_i(g1a[2], g2a[2]);
                float g3 = sA * sg1 * dec_i(g1a[3], g2a[3]);
                float u2 = sA * su0 * dec_i(u1a[2], u2a[2]);
                float u3 = sA * su1 * dec_i(u1a[3], u2a[3]);
                *(float2*)&d_hmid[(size_t)(e * N_TOK + r1) * FDIM + cl] =
                    make_float2(silu_f(g2) * u2, silu_f(g3) * u3);
            }
        }
    }
}

// ---------------- GEMM2 (int8): hmid @ down^T -> y fp32 ----------------------
// CTA: 128 slots x 64 y cols.
__global__ __launch_bounds__(256)
void gemm2_i8() {
    int e   = blockIdx.z;
    int cnt = d_cnt[e];
    int m0  = blockIdx.y * 128;
    if (m0 >= cnt) return;
    int j0  = blockIdx.x * 64;

    extern __shared__ __align__(16) unsigned char smem[];
    uint32_t sbase = (uint32_t)__cvta_generic_to_shared(smem);

    int tid  = threadIdx.x;
    int lane = tid & 31;
    int wid  = tid >> 5;
    int warp_m = wid & 3;
    int warp_n = wid >> 2;

    int  m_l  = tid >> 1;
    int  half = tid & 1;
    int  am   = m0 + m_l;
    bool av   = (am < cnt);
    size_t slotrow = (size_t)e * N_TOK + (av ? am : 0);
    const uint4* a1p = (const uint4*)(d_hq1 + slotrow * 256) + half * 2;
    const uint4* a2p = (const uint4*)(d_hq2 + slotrow * 256) + half * 2;
    uint32_t sts_a = (uint32_t)(m_l * LDR + half * 32);

    int b_l = tid >> 2;
    int bq  = tid & 3;
    size_t drowbase = ((size_t)e * 1024 + j0 + b_l) * 256;
    const uint4* b1p = (const uint4*)(d_dq1 + drowbase) + bq;
    const uint4* b2p = (const uint4*)(d_dq2 + drowbase) + bq;
    uint32_t sts_b = (uint32_t)(b_l * LDR + bq * 16);

    uint4 pa1[2], pa2[2], pb1, pb2;
    const uint4 zu = make_uint4(0, 0, 0, 0);
    pa1[0] = av ? a1p[0] : zu;  pa1[1] = av ? a1p[1] : zu;
    pa2[0] = av ? a2p[0] : zu;  pa2[1] = av ? a2p[1] : zu;
    pb1 = b1p[0];  pb2 = b2p[0];

    *(uint4*)(smem + sts_a)              = pa1[0];
    *(uint4*)(smem + sts_a + 16)         = pa1[1];
    *(uint4*)(smem + ASZ8 + sts_a)       = pa2[0];
    *(uint4*)(smem + ASZ8 + sts_a + 16)  = pa2[1];
    *(uint4*)(smem + 2 * ASZ8 + sts_b)          = pb1;
    *(uint4*)(smem + 2 * ASZ8 + BSZ8 + sts_b)   = pb2;
    __syncthreads();

    int acc1[2][4][4], acc2[2][4][4];
#pragma unroll
    for (int i = 0; i < 2; ++i)
#pragma unroll
        for (int j = 0; j < 4; ++j)
#pragma unroll
            for (int q = 0; q < 4; ++q) { acc1[i][j][q] = 0; acc2[i][j][q] = 0; }

    uint32_t a_lane = (warp_m * 32 + (lane & 15)) * LDR + (lane >> 4) * 16;
    uint32_t b_lane[2];
#pragma unroll
    for (int bp = 0; bp < 2; ++bp)
        b_lane[bp] = (warp_n * 32 + bp * 16 + (lane & 7) + ((lane >> 4) & 1) * 8) * LDR
                     + ((lane >> 3) & 1) * 16;

    const int KT = 16;
    uint32_t bufo = 0;
    for (int kt = 0; kt < KT; ++kt) {
        bool more = (kt + 1 < KT);
        if (more) {
            int ki = (kt + 1) * 4;
            pa1[0] = av ? a1p[ki]     : zu;
            pa1[1] = av ? a1p[ki + 1] : zu;
            pa2[0] = av ? a2p[ki]     : zu;
            pa2[1] = av ? a2p[ki + 1] : zu;
            pb1 = b1p[ki];
            pb2 = b2p[ki];
        }

        CHUNK_S8(bufo, 0);
        CHUNK_S8(bufo, 32);

        if (more) {
            uint32_t nb = bufo ^ STG8;
            *(uint4*)(smem + nb + sts_a)              = pa1[0];
            *(uint4*)(smem + nb + sts_a + 16)         = pa1[1];
            *(uint4*)(smem + nb + ASZ8 + sts_a)       = pa2[0];
            *(uint4*)(smem + nb + ASZ8 + sts_a + 16)  = pa2[1];
            *(uint4*)(smem + nb + 2 * ASZ8 + sts_b)        = pb1;
            *(uint4*)(smem + nb + 2 * ASZ8 + BSZ8 + sts_b) = pb2;
            __syncthreads();
            bufo = nb;
        }
    }

    int rrow = warp_m * 32 + (lane >> 2);
#pragma unroll
    for (int mt = 0; mt < 2; ++mt) {
        int r0 = m0 + rrow + mt * 16;
        int r1 = r0 + 8;
        float sA0 = (r0 < cnt) ? d_sh[(size_t)e * N_TOK + r0] : 0.f;
        float sA1 = (r1 < cnt) ? d_sh[(size_t)e * N_TOK + r1] : 0.f;
#pragma unroll
        for (int nt = 0; nt < 4; ++nt) {
            int c = j0 + warp_n * 32 + nt * 8 + (lane & 3) * 2;
            float sB0 = d_sd[e * 1024 + c];
            float sB1 = d_sd[e * 1024 + c + 1];
            if (r0 < cnt) {
                *(float2*)&d_y[(size_t)(e * N_TOK + r0) * HDIM + c] = make_float2(
                    sA0 * sB0 * dec_i(acc1[mt][nt][0], acc2[mt][nt][0]),
                    sA0 * sB1 * dec_i(acc1[mt][nt][1], acc2[mt][nt][1]));
            }
            if (r1 < cnt) {
                *(float2*)&d_y[(size_t)(e * N_TOK + r1) * HDIM + c] = make_float2(
                    sA1 * sB0 * dec_i(acc1[mt][nt][2], acc2[mt][nt][2]),
                    sA1 * sB1 * dec_i(acc1[mt][nt][3], acc2[mt][nt][3]));
            }
        }
    }
}

// out[n] = w0 * y[slot0] + w1 * y[slot1]
__global__ void combine_kernel(float* __restrict__ out) {
    int n = blockIdx.x;
    int q = threadIdx.x;
    int   s0 = d_pair_slot[2 * n],     s1 = d_pair_slot[2 * n + 1];
    float w0 = d_pair_w[2 * n],        w1 = d_pair_w[2 * n + 1];

    float4 a = *(const float4*)&d_y[(size_t)s0 * HDIM + q * 4];
    float4 r;
    r.x = w0 * a.x; r.y = w0 * a.y; r.z = w0 * a.z; r.w = w0 * a.w;
    if (s1 >= 0) {
        float4 b = *(const float4*)&d_y[(size_t)s1 * HDIM + q * 4];
        r.x = fmaf(w1, b.x, r.x); r.y = fmaf(w1, b.y, r.y);
        r.z = fmaf(w1, b.z, r.z); r.w = fmaf(w1, b.w, r.w);
    }
    *(float4*)&out[(size_t)n * HDIM + q * 4] = r;
}

// ---------------- launcher ---------------------------------------------------
extern "C" void kernel_launch(void* const* d_in, const int* in_sizes, int n_in,
                              void* d_out, int out_size) {
    const float* x   = (const float*)d_in[0];
    const float* gw  = (const float*)d_in[1];
    const float* gup = (const float*)d_in[2];
    const float* dwn = (const float*)d_in[3];
    const float* sim = (const float*)d_in[4];
    float* out = (float*)d_out;

    cudaFuncSetAttribute(gemm1_i8,
                         cudaFuncAttributeMaxDynamicSharedMemorySize, SMEM8);
    cudaFuncSetAttribute(gemm2_i8,
                         cudaFuncAttributeMaxDynamicSharedMemorySize, SMEM8);

    // quantize inputs/weights (independent of routing)
    uint32_t *gq1, *gq2, *dq1, *dq2, *xq1, *xq2;
    float *sg, *sd, *sx;
    cudaGetSymbolAddress((void**)&gq1, d_gq1);
    cudaGetSymbolAddress((void**)&gq2, d_gq2);
    cudaGetSymbolAddress((void**)&sg,  d_sg);
    cudaGetSymbolAddress((void**)&dq1, d_dq1);
    cudaGetSymbolAddress((void**)&dq2, d_dq2);
    cudaGetSymbolAddress((void**)&sd,  d_sd);
    cudaGetSymbolAddress((void**)&xq1, d_xq1);
    cudaGetSymbolAddress((void**)&xq2, d_xq2);
    cudaGetSymbolAddress((void**)&sx,  d_sx);

    quant_rows<<<NE * 2048, 256>>>(gup, gq1, gq2, sg);
    quant_rows<<<NE * 1024, 256>>>(dwn, dq1, dq2, sd);
    quant_rows<<<N_TOK, 256>>>(x, xq1, xq2, sx);

    init_kernel<<<1, 32>>>();
    router_kernel<<<N_TOK, 128>>>(x, gw);
    map_kernel<<<1, 32>>>(sim);
    assign_kernel<<<(N_TOK + 255) / 256, 256>>>();

    gemm1_i8<<<dim3(FDIM / 32, N_TOK / 128, NE), 256, SMEM8>>>();
    quant_h_kernel<<<dim3(N_TOK, NE), 256>>>();
    gemm2_i8<<<dim3(HDIM / 64, N_TOK / 128, NE), 256, SMEM8>>>();
    combine_kernel<<<N_TOK, 256>>>(out);
}